// round 13
// baseline (speedup 1.0000x reference)
#include <cuda_runtime.h>

#define BATCH 64
#define H0 256
#define W0 256
#define H1 128
#define W1 128
#define NPIX0 (H0*W0)
#define NPIX1 (H1*W1)

typedef unsigned long long ull;

// ---- packed f32x2 helpers ----
__device__ __forceinline__ ull f2pack(float a, float b) {
    ull r; asm("mov.b64 %0, {%1, %2};" : "=l"(r) : "f"(a), "f"(b)); return r;
}
__device__ __forceinline__ void ffma2(ull& d, ull a, ull b) {
    asm("fma.rn.f32x2 %0, %1, %2, %0;" : "+l"(d) : "l"(a), "l"(b));
}
__device__ __forceinline__ float2 f2unpack(ull v) {
    float lo, hi; asm("mov.b64 {%0, %1}, %2;" : "=f"(lo), "=f"(hi) : "l"(v));
    return make_float2(lo, hi);
}

// ---------------- scratch (device globals: no allocations allowed) ----------
__device__ float g_t2[BATCH*16*NPIX1];    // conv2 out (67 MB)
__device__ float g_t3[BATCH*16*NPIX1];    // conv3 out (67 MB)
__device__ float g_part[BATCH*16*16];     // 32x32-block sums of fb (pool cells)
__device__ float g_phi[BATCH*3];          // combined head coefficients
__device__ float g_tmp[BATCH*NPIX0];      // horizontal blur intermediate (17 MB)

// ---- dummy kernels to shift the ncu capture slot onto conv12 ---------------
__global__ void warm_kernel() {}

// =====================================================================
// Fused conv1 (3->16, 3x3, s1, SAME, relu) + conv2 (16->16, 3x3, s2,
// SAME pad_lo=0, relu). One block -> 32x32 conv2 output tile; each
// thread owns a 2x2 output quad so each weight fetch serves 4 pixels
// and the quad's 5x5 s_mid patch is shared.
// =====================================================================
#define C12_SMEM_FLOATS (3*67*68 + 8*65*66 + 27*16 + 144*16 + 32)

__global__ void __launch_bounds__(256, 1)
conv12_kernel(const float* __restrict__ x,
              const float* __restrict__ w1,
              const float* __restrict__ b1,
              const float* __restrict__ w2,
              const float* __restrict__ b2) {
    extern __shared__ float sm[];
    float* s_x   = sm;                     // [3][67][68]  (67 rows x 67 cols used)
    float* s_mid = s_x + 3*67*68;          // [8][65][66]  (65 rows x 65 cols used)
    float* s_w1  = s_mid + 8*65*66;        // [27][16]
    float* s_w2  = s_w1 + 27*16;           // [144][16]
    float* s_b1  = s_w2 + 144*16;          // [16]
    float* s_b2  = s_b1 + 16;              // [16]

    const int b = blockIdx.z;
    const int ox0 = blockIdx.x * 32, oy0 = blockIdx.y * 32;
    const int ix0 = ox0 * 2, iy0 = oy0 * 2;   // conv1-output-space tile origin
    const int tid = threadIdx.y * 16 + threadIdx.x;
    const int ty = threadIdx.y, tx = threadIdx.x;

    for (int i = tid; i < 27*16; i += 256) {
        int oc = i & 15, k = i >> 4;
        s_w1[k*16 + oc] = w1[oc*27 + k];
    }
    for (int i = tid; i < 144*16; i += 256) {
        int oc = i & 15, k = i >> 4;
        s_w2[k*16 + oc] = w2[oc*144 + k];
    }
    if (tid < 16) { s_b1[tid] = b1[tid]; s_b2[tid] = b2[tid]; }

    // x halo: 3 x 67 x 68 (global rows iy0-1 .. iy0+65, cols ix0-1 .. ix0+66)
    for (int i = tid; i < 3*67*68; i += 256) {
        int c = i / 4556, r = i % 4556;
        int yy = r / 68, xx = r % 68;
        int gy = iy0 + yy - 1, gx = ix0 + xx - 1;
        float v = 0.f;
        if (gy >= 0 && gy < H0 && gx >= 0 && gx < W0)
            v = x[((b*3 + c)*H0 + gy)*W0 + gx];
        s_x[(c*67 + yy)*68 + xx] = v;
    }

    // conv2 accumulators: 2x2 quad x 16 oc as 8 packed pairs each
    ull acc00[8], acc01[8], acc10[8], acc11[8];
    #pragma unroll
    for (int j = 0; j < 8; j++) { acc00[j] = 0ull; acc01[j] = 0ull; acc10[j] = 0ull; acc11[j] = 0ull; }

    for (int occ = 0; occ < 16; occ += 8) {
        __syncthreads();
        // ---- conv1 for channels occ..occ+7 over 65x65 positions, x-paired ----
        for (int i = tid; i < 65*33; i += 256) {
            const int yy = i / 33;
            const int xx0 = (i - yy*33) * 2;       // positions xx0, xx0+1
            ull a0[4], a1[4];
            #pragma unroll
            for (int j = 0; j < 4; j++) {
                ull bb = f2pack(s_b1[occ + 2*j], s_b1[occ + 2*j + 1]);
                a0[j] = bb; a1[j] = bb;
            }
            #pragma unroll
            for (int c = 0; c < 3; c++)
                #pragma unroll
                for (int ky = 0; ky < 3; ky++) {
                    // aligned 4-float row segment [xx0 .. xx0+3]
                    const float* rp = &s_x[(c*67 + yy + ky)*68 + xx0];
                    float2 q0 = *(const float2*)rp;
                    float2 q1 = *(const float2*)(rp + 2);
                    float v0 = q0.x, v1 = q0.y, v2 = q1.x, v3 = q1.y;
                    #pragma unroll
                    for (int kx = 0; kx < 3; kx++) {
                        float va = (kx == 0) ? v0 : (kx == 1 ? v1 : v2);
                        float vb = (kx == 0) ? v1 : (kx == 1 ? v2 : v3);
                        ull vba = f2pack(va, va);
                        ull vbb = f2pack(vb, vb);
                        const ulonglong2* wr2 = (const ulonglong2*)&s_w1[(c*9 + ky*3 + kx)*16 + occ];
                        ulonglong2 wa = wr2[0], wb = wr2[1];
                        ffma2(a0[0], vba, wa.x); ffma2(a1[0], vbb, wa.x);
                        ffma2(a0[1], vba, wa.y); ffma2(a1[1], vbb, wa.y);
                        ffma2(a0[2], vba, wb.x); ffma2(a1[2], vbb, wb.x);
                        ffma2(a0[3], vba, wb.y); ffma2(a1[3], vbb, wb.y);
                    }
                }
            // conv2 SAME pad-hi: zero conv1 outputs beyond the image edge
            const int gy1 = iy0 + yy;
            const int gx10 = ix0 + xx0;
            const bool v0ok = (gy1 < H0) && (gx10 < W0);
            const bool v1ok = (gy1 < H0) && (gx10 + 1 < W0);
            #pragma unroll
            for (int j = 0; j < 4; j++) {
                float2 r0 = f2unpack(a0[j]);   // pos0: ch 2j, 2j+1
                float2 r1 = f2unpack(a1[j]);   // pos1
                float2 stA = make_float2(v0ok ? fmaxf(r0.x, 0.f) : 0.f,
                                         v1ok ? fmaxf(r1.x, 0.f) : 0.f);
                float2 stB = make_float2(v0ok ? fmaxf(r0.y, 0.f) : 0.f,
                                         v1ok ? fmaxf(r1.y, 0.f) : 0.f);
                // xx0 even, row stride 66 even -> aligned STS.64 (col 65 = pad, never read)
                *(float2*)&s_mid[((2*j)*65 + yy)*66 + xx0]   = stA;
                *(float2*)&s_mid[((2*j+1)*65 + yy)*66 + xx0] = stB;
            }
        }
        __syncthreads();
        // ---- conv2 partial accumulation over these 8 input channels ----
        #pragma unroll 2
        for (int c = 0; c < 8; c++) {
            // 5x6 patch covering the 2x2 output quad (cols 4tx..4tx+5, rows 4ty..4ty+4)
            const float* base = &s_mid[(c*65 + 4*ty)*66 + 4*tx];
            float u[5][6];
            #pragma unroll
            for (int r = 0; r < 5; r++) {
                float2 qa = *(const float2*)&base[r*66];
                float2 qb = *(const float2*)&base[r*66 + 2];
                float2 qc = *(const float2*)&base[r*66 + 4];
                u[r][0] = qa.x; u[r][1] = qa.y; u[r][2] = qb.x;
                u[r][3] = qb.y; u[r][4] = qc.x; u[r][5] = qc.y;
            }
            #pragma unroll
            for (int ky = 0; ky < 3; ky++)
                #pragma unroll
                for (int kx = 0; kx < 3; kx++) {
                    const ulonglong2* wr2 = (const ulonglong2*)&s_w2[((occ + c)*9 + ky*3 + kx)*16];
                    ulonglong2 w0 = wr2[0], w1q = wr2[1], w2q = wr2[2], w3q = wr2[3];
                    ull v00 = f2pack(u[ky][kx],     u[ky][kx]);
                    ull v01 = f2pack(u[ky][kx+2],   u[ky][kx+2]);
                    ull v10 = f2pack(u[ky+2][kx],   u[ky+2][kx]);
                    ull v11 = f2pack(u[ky+2][kx+2], u[ky+2][kx+2]);
                    ffma2(acc00[0], v00, w0.x);  ffma2(acc01[0], v01, w0.x);
                    ffma2(acc10[0], v10, w0.x);  ffma2(acc11[0], v11, w0.x);
                    ffma2(acc00[1], v00, w0.y);  ffma2(acc01[1], v01, w0.y);
                    ffma2(acc10[1], v10, w0.y);  ffma2(acc11[1], v11, w0.y);
                    ffma2(acc00[2], v00, w1q.x); ffma2(acc01[2], v01, w1q.x);
                    ffma2(acc10[2], v10, w1q.x); ffma2(acc11[2], v11, w1q.x);
                    ffma2(acc00[3], v00, w1q.y); ffma2(acc01[3], v01, w1q.y);
                    ffma2(acc10[3], v10, w1q.y); ffma2(acc11[3], v11, w1q.y);
                    ffma2(acc00[4], v00, w2q.x); ffma2(acc01[4], v01, w2q.x);
                    ffma2(acc10[4], v10, w2q.x); ffma2(acc11[4], v11, w2q.x);
                    ffma2(acc00[5], v00, w2q.y); ffma2(acc01[5], v01, w2q.y);
                    ffma2(acc10[5], v10, w2q.y); ffma2(acc11[5], v11, w2q.y);
                    ffma2(acc00[6], v00, w3q.x); ffma2(acc01[6], v01, w3q.x);
                    ffma2(acc10[6], v10, w3q.x); ffma2(acc11[6], v11, w3q.x);
                    ffma2(acc00[7], v00, w3q.y); ffma2(acc01[7], v01, w3q.y);
                    ffma2(acc10[7], v10, w3q.y); ffma2(acc11[7], v11, w3q.y);
                }
        }
    }

    const int gy = oy0 + 2*ty, gx = ox0 + 2*tx;
    #pragma unroll
    for (int j = 0; j < 8; j++) {
        float2 a00 = f2unpack(acc00[j]), a01 = f2unpack(acc01[j]);
        float2 a10 = f2unpack(acc10[j]), a11 = f2unpack(acc11[j]);
        float b0 = s_b2[2*j], b1q = s_b2[2*j+1];
        float* p0 = &g_t2[((b*16 + 2*j)*H1 + gy)*W1 + gx];
        *(float2*)p0        = make_float2(fmaxf(a00.x + b0, 0.f), fmaxf(a01.x + b0, 0.f));
        *(float2*)(p0 + W1) = make_float2(fmaxf(a10.x + b0, 0.f), fmaxf(a11.x + b0, 0.f));
        float* p1 = p0 + NPIX1;
        *(float2*)p1        = make_float2(fmaxf(a00.y + b1q, 0.f), fmaxf(a01.y + b1q, 0.f));
        *(float2*)(p1 + W1) = make_float2(fmaxf(a10.y + b1q, 0.f), fmaxf(a11.y + b1q, 0.f));
    }
}

// =====================================================================
// conv3: 16->16, 3x3, s1, SAME, relu. 32x32 tile, 2x2 pixels per thread.
// =====================================================================
#define C3_SMEM_FLOATS (16*34*36 + 144*16 + 16)

__global__ void __launch_bounds__(256)
conv3_kernel(const float* __restrict__ w,
             const float* __restrict__ bias) {
    extern __shared__ float sm[];
    float* s_in = sm;                 // [16][34][36]
    float* s_w  = s_in + 16*34*36;    // [144][16]
    float* s_b  = s_w + 144*16;       // [16]

    const int b = blockIdx.z;
    const int oy0 = blockIdx.y * 32, ox0 = blockIdx.x * 32;
    const int tid = threadIdx.y * 16 + threadIdx.x;
    const int ty = threadIdx.y, tx = threadIdx.x;

    for (int i = tid; i < 144*16; i += 256) {
        int oc = i & 15, k = i >> 4;
        s_w[k*16 + oc] = w[oc*144 + k];
    }
    if (tid < 16) s_b[tid] = bias[tid];
    for (int i = tid; i < 16*34*34; i += 256) {
        int c = i / 1156, r = i % 1156;
        int yy = r / 34, xx = r % 34;
        int gy = oy0 + yy - 1, gx = ox0 + xx - 1;
        float v = 0.f;
        if (gy >= 0 && gy < H1 && gx >= 0 && gx < W1)
            v = g_t2[((b*16 + c)*H1 + gy)*W1 + gx];
        s_in[(c*34 + yy)*36 + xx] = v;
    }
    __syncthreads();

    ull acc0[8], acc1[8], acc2[8], acc3[8];
    #pragma unroll
    for (int j = 0; j < 8; j++) {
        ull bb = f2pack(s_b[2*j], s_b[2*j+1]);
        acc0[j] = bb; acc1[j] = bb; acc2[j] = bb; acc3[j] = bb;
    }

    #pragma unroll 2
    for (int c = 0; c < 16; c++) {
        const float* base = &s_in[(c*34 + 2*ty)*36 + 2*tx];
        float vv[4][4];
        #pragma unroll
        for (int iy = 0; iy < 4; iy++) {
            float2 qa = *(const float2*)&base[iy*36];
            float2 qb = *(const float2*)&base[iy*36 + 2];
            vv[iy][0] = qa.x; vv[iy][1] = qa.y; vv[iy][2] = qb.x; vv[iy][3] = qb.y;
        }
        #pragma unroll
        for (int ky = 0; ky < 3; ky++)
            #pragma unroll
            for (int kx = 0; kx < 3; kx++) {
                const ulonglong2* wr2 = (const ulonglong2*)&s_w[(c*9 + ky*3 + kx)*16];
                ulonglong2 w0 = wr2[0], w1q = wr2[1], w2q = wr2[2], w3q = wr2[3];
                ull v00 = f2pack(vv[ky][kx],     vv[ky][kx]);
                ull v01 = f2pack(vv[ky][kx+1],   vv[ky][kx+1]);
                ull v10 = f2pack(vv[ky+1][kx],   vv[ky+1][kx]);
                ull v11 = f2pack(vv[ky+1][kx+1], vv[ky+1][kx+1]);
                ffma2(acc0[0], v00, w0.x); ffma2(acc0[1], v00, w0.y);
                ffma2(acc0[2], v00, w1q.x); ffma2(acc0[3], v00, w1q.y);
                ffma2(acc0[4], v00, w2q.x); ffma2(acc0[5], v00, w2q.y);
                ffma2(acc0[6], v00, w3q.x); ffma2(acc0[7], v00, w3q.y);
                ffma2(acc1[0], v01, w0.x); ffma2(acc1[1], v01, w0.y);
                ffma2(acc1[2], v01, w1q.x); ffma2(acc1[3], v01, w1q.y);
                ffma2(acc1[4], v01, w2q.x); ffma2(acc1[5], v01, w2q.y);
                ffma2(acc1[6], v01, w3q.x); ffma2(acc1[7], v01, w3q.y);
                ffma2(acc2[0], v10, w0.x); ffma2(acc2[1], v10, w0.y);
                ffma2(acc2[2], v10, w1q.x); ffma2(acc2[3], v10, w1q.y);
                ffma2(acc2[4], v10, w2q.x); ffma2(acc2[5], v10, w2q.y);
                ffma2(acc2[6], v10, w3q.x); ffma2(acc2[7], v10, w3q.y);
                ffma2(acc3[0], v11, w0.x); ffma2(acc3[1], v11, w0.y);
                ffma2(acc3[2], v11, w1q.x); ffma2(acc3[3], v11, w1q.y);
                ffma2(acc3[4], v11, w2q.x); ffma2(acc3[5], v11, w2q.y);
                ffma2(acc3[6], v11, w3q.x); ffma2(acc3[7], v11, w3q.y);
            }
    }

    const int gy = oy0 + 2*ty, gx = ox0 + 2*tx;
    #pragma unroll
    for (int j = 0; j < 8; j++) {
        float2 a0 = f2unpack(acc0[j]), a1 = f2unpack(acc1[j]);
        float2 a2 = f2unpack(acc2[j]), a3 = f2unpack(acc3[j]);
        float* p0 = &g_t3[((b*16 + 2*j)*H1 + gy)*W1 + gx];
        *(float2*)p0        = make_float2(fmaxf(a0.x, 0.f), fmaxf(a1.x, 0.f));
        *(float2*)(p0 + W1) = make_float2(fmaxf(a2.x, 0.f), fmaxf(a3.x, 0.f));
        float* p1 = p0 + NPIX1;
        *(float2*)p1        = make_float2(fmaxf(a0.y, 0.f), fmaxf(a1.y, 0.f));
        *(float2*)(p1 + W1) = make_float2(fmaxf(a2.y, 0.f), fmaxf(a3.y, 0.f));
    }
}

// =====================================================================
// Fused depthwise 3x3 + relu + pointwise 1x1 + relu + 32x32 pool sum.
// =====================================================================
#define DW_SMEM_FLOATS (16*34*36 + 144 + 256 + 16 + 16 + 128)

__global__ void __launch_bounds__(256)
dwpw_kernel(const float* __restrict__ wd,
            const float* __restrict__ bd,
            const float* __restrict__ wp,
            const float* __restrict__ bp) {
    extern __shared__ float sm[];
    float* s_in  = sm;                  // [16][34][36]
    float* s_wd  = s_in + 16*34*36;     // [16][9]
    float* s_wp  = s_wd + 144;          // [16][16]  [ic][oc]
    float* s_bd  = s_wp + 256;          // [16]
    float* s_bp  = s_bd + 16;           // [16]
    float* s_red = s_bp + 16;           // [8][16]

    const int b = blockIdx.z;
    const int oy0 = blockIdx.y * 32, ox0 = blockIdx.x * 32;
    const int tid = threadIdx.y * 16 + threadIdx.x;
    const int ty = threadIdx.y, tx = threadIdx.x;

    if (tid < 144) s_wd[tid] = wd[tid];
    {
        int oc = tid >> 4, ic = tid & 15;
        s_wp[ic*16 + oc] = wp[oc*16 + ic];
    }
    if (tid < 16) { s_bd[tid] = bd[tid]; s_bp[tid] = bp[tid]; }
    for (int i = tid; i < 16*34*34; i += 256) {
        int c = i / 1156, r = i % 1156;
        int yy = r / 34, xx = r % 34;
        int gy = oy0 + yy - 1, gx = ox0 + xx - 1;
        float v = 0.f;
        if (gy >= 0 && gy < H1 && gx >= 0 && gx < W1)
            v = g_t3[((b*16 + c)*H1 + gy)*W1 + gx];
        s_in[(c*34 + yy)*36 + xx] = v;
    }
    __syncthreads();

    ull acc0[8], acc1[8], acc2[8], acc3[8];
    #pragma unroll
    for (int j = 0; j < 8; j++) {
        ull bb = f2pack(s_bp[2*j], s_bp[2*j+1]);
        acc0[j] = bb; acc1[j] = bb; acc2[j] = bb; acc3[j] = bb;
    }

    #pragma unroll 2
    for (int c = 0; c < 16; c++) {
        const float* base = &s_in[(c*34 + 2*ty)*36 + 2*tx];
        float vv[4][4];
        #pragma unroll
        for (int iy = 0; iy < 4; iy++) {
            float2 qa = *(const float2*)&base[iy*36];
            float2 qb = *(const float2*)&base[iy*36 + 2];
            vv[iy][0] = qa.x; vv[iy][1] = qa.y; vv[iy][2] = qb.x; vv[iy][3] = qb.y;
        }
        ull d01 = f2pack(s_bd[c], s_bd[c]);
        ull d23 = d01;
        #pragma unroll
        for (int ky = 0; ky < 3; ky++)
            #pragma unroll
            for (int kx = 0; kx < 3; kx++) {
                float wvv = s_wd[c*9 + ky*3 + kx];
                ull wb = f2pack(wvv, wvv);
                ull va = f2pack(vv[ky][kx],   vv[ky][kx+1]);
                ull vb = f2pack(vv[ky+1][kx], vv[ky+1][kx+1]);
                ffma2(d01, va, wb);
                ffma2(d23, vb, wb);
            }
        float2 dab = f2unpack(d01), dcd = f2unpack(d23);
        float dw0 = fmaxf(dab.x, 0.f), dw1 = fmaxf(dab.y, 0.f);
        float dw2 = fmaxf(dcd.x, 0.f), dw3 = fmaxf(dcd.y, 0.f);
        ull p0 = f2pack(dw0, dw0), p1 = f2pack(dw1, dw1);
        ull p2 = f2pack(dw2, dw2), p3 = f2pack(dw3, dw3);
        const ulonglong2* wr2 = (const ulonglong2*)&s_wp[c*16];
        ulonglong2 w0 = wr2[0], w1q = wr2[1], w2q = wr2[2], w3q = wr2[3];
        ffma2(acc0[0], p0, w0.x); ffma2(acc0[1], p0, w0.y);
        ffma2(acc0[2], p0, w1q.x); ffma2(acc0[3], p0, w1q.y);
        ffma2(acc0[4], p0, w2q.x); ffma2(acc0[5], p0, w2q.y);
        ffma2(acc0[6], p0, w3q.x); ffma2(acc0[7], p0, w3q.y);
        ffma2(acc1[0], p1, w0.x); ffma2(acc1[1], p1, w0.y);
        ffma2(acc1[2], p1, w1q.x); ffma2(acc1[3], p1, w1q.y);
        ffma2(acc1[4], p1, w2q.x); ffma2(acc1[5], p1, w2q.y);
        ffma2(acc1[6], p1, w3q.x); ffma2(acc1[7], p1, w3q.y);
        ffma2(acc2[0], p2, w0.x); ffma2(acc2[1], p2, w0.y);
        ffma2(acc2[2], p2, w1q.x); ffma2(acc2[3], p2, w1q.y);
        ffma2(acc2[4], p2, w2q.x); ffma2(acc2[5], p2, w2q.y);
        ffma2(acc2[6], p2, w3q.x); ffma2(acc2[7], p2, w3q.y);
        ffma2(acc3[0], p3, w0.x); ffma2(acc3[1], p3, w0.y);
        ffma2(acc3[2], p3, w1q.x); ffma2(acc3[3], p3, w1q.y);
        ffma2(acc3[4], p3, w2q.x); ffma2(acc3[5], p3, w2q.y);
        ffma2(acc3[6], p3, w3q.x); ffma2(acc3[7], p3, w3q.y);
    }

    float t[16];
    #pragma unroll
    for (int j = 0; j < 8; j++) {
        float2 a0 = f2unpack(acc0[j]), a1 = f2unpack(acc1[j]);
        float2 a2 = f2unpack(acc2[j]), a3 = f2unpack(acc3[j]);
        t[2*j]   = fmaxf(a0.x,0.f) + fmaxf(a1.x,0.f) + fmaxf(a2.x,0.f) + fmaxf(a3.x,0.f);
        t[2*j+1] = fmaxf(a0.y,0.f) + fmaxf(a1.y,0.f) + fmaxf(a2.y,0.f) + fmaxf(a3.y,0.f);
    }
    #pragma unroll
    for (int oc = 0; oc < 16; oc++) {
        float v = t[oc];
        #pragma unroll
        for (int o = 16; o > 0; o >>= 1) v += __shfl_xor_sync(0xffffffffu, v, o);
        t[oc] = v;
    }
    const int warp = tid >> 5, lane = tid & 31;
    if (lane == 0) {
        #pragma unroll
        for (int oc = 0; oc < 16; oc++) s_red[warp*16 + oc] = t[oc];
    }
    __syncthreads();
    if (tid < 16) {
        float s = 0.f;
        #pragma unroll
        for (int w8 = 0; w8 < 8; w8++) s += s_red[w8*16 + tid];
        g_part[(b*16 + tid)*16 + blockIdx.y*4 + blockIdx.x] = s;
    }
}

// -------- combined head coefficients: phi = (phi1+phi2+phi3)/3 --------------
__global__ void phi_kernel(const float* __restrict__ wf1, const float* __restrict__ bf1,
                           const float* __restrict__ wf2, const float* __restrict__ bf2,
                           const float* __restrict__ wf3, const float* __restrict__ bf3) {
    const int b = blockIdx.x;
    const int t = threadIdx.x;
    const int c = t >> 4, ch = t & 15;
    __shared__ float red[48];
    float S = 0.f;
    if (t < 48) {
        const float* part = &g_part[(b*16 + ch)*16];
        float m[16];
        float sum16 = 0.f;
        #pragma unroll
        for (int p = 0; p < 16; p++) {
            m[p] = part[p] * (1.0f / 1024.0f);
            sum16 += m[p];
            S = fmaf(m[p], wf3[c*256 + ch*16 + p], S);
        }
        S = fmaf(sum16 * (1.f / 16.f), wf1[c*16 + ch], S);
        #pragma unroll
        for (int i = 0; i < 2; i++)
            #pragma unroll
            for (int j = 0; j < 2; j++) {
                float f2v = 0.25f * (m[(2*i)*4 + 2*j] + m[(2*i)*4 + 2*j + 1] +
                                     m[(2*i+1)*4 + 2*j] + m[(2*i+1)*4 + 2*j + 1]);
                S = fmaf(f2v, wf2[c*64 + ch*4 + i*2 + j], S);
            }
        red[t] = S;
    }
    __syncthreads();
    if (t < 3) {
        float tot = bf1[t] + bf2[t] + bf3[t];
        #pragma unroll
        for (int i = 0; i < 16; i++) tot += red[t*16 + i];
        g_phi[b*3 + t] = tot * (1.f / 3.f);
    }
}

// -------- fused grayscale + horizontal 21-tap Gaussian (reflect-101) --------
__global__ void grayblurh_kernel(const float* __restrict__ x, float* __restrict__ out) {
    __shared__ float row[256];
    __shared__ float sw[21];
    const int b = blockIdx.y, y = blockIdx.x;
    const int tx = threadIdx.x;
    if (tx < 21) {
        float t = (float)tx - 10.f;
        sw[tx] = expf(-(t * t) / 24.5f);
    }
    const float p0 = g_phi[b*3 + 0], p1 = g_phi[b*3 + 1], p2 = g_phi[b*3 + 2];
    const int i = y * 256 + tx;
    float v = p0 * x[(b*3 + 0)*NPIX0 + i]
            + p1 * x[(b*3 + 1)*NPIX0 + i]
            + p2 * x[(b*3 + 2)*NPIX0 + i];
    out[(b*3 + 1)*NPIX0 + i] = v;   // i_gray (channel 1)
    row[tx] = v;
    __syncthreads();
    float wsum = 0.f;
    #pragma unroll
    for (int t = 0; t < 21; t++) wsum += sw[t];
    float acc = 0.f;
    #pragma unroll
    for (int t = 0; t < 21; t++) {
        int xx = tx + t - 10;
        xx = xx < 0 ? -xx : (xx > 255 ? 510 - xx : xx);
        acc = fmaf(sw[t], row[xx], acc);
    }
    g_tmp[(b*256 + y)*256 + tx] = acc / wsum;
}

// -------- vertical 21-tap Gaussian + base/detail writes ---------------------
__global__ void blurv_kernel(float* __restrict__ out) {
    __shared__ float tile[84][32];
    __shared__ float sw[21];
    const int b = blockIdx.z;
    const int x0 = blockIdx.x * 32, y0 = blockIdx.y * 64;
    const int tid = threadIdx.y * 32 + threadIdx.x;
    if (tid < 21) {
        float t = (float)tid - 10.f;
        sw[tid] = expf(-(t * t) / 24.5f);
    }
    for (int i = tid; i < 84 * 32; i += 256) {
        int yy = i >> 5, xx = i & 31;
        int gy = y0 + yy - 10;
        gy = gy < 0 ? -gy : (gy > 255 ? 510 - gy : gy);
        tile[yy][xx] = g_tmp[(b*256 + gy)*256 + x0 + xx];
    }
    __syncthreads();
    float wsum = 0.f;
    #pragma unroll
    for (int t = 0; t < 21; t++) wsum += sw[t];
    const float inv = 1.f / wsum;
    const int tx = threadIdx.x;
    for (int r = 0; r < 8; r++) {
        const int ly = threadIdx.y * 8 + r;
        float acc = 0.f;
        #pragma unroll
        for (int t = 0; t < 21; t++) acc = fmaf(sw[t], tile[ly + t][tx], acc);
        const float base = acc * inv;
        const int gy = y0 + ly, gx = x0 + tx;
        const int idx = (b*3)*NPIX0 + gy*256 + gx;
        const float ig = out[idx + NPIX0];
        out[idx] = base;                  // base   (channel 0)
        out[idx + 2*NPIX0] = ig - base;   // detail (channel 2)
    }
}

// ---------------------------------------------------------------------------
extern "C" void kernel_launch(void* const* d_in, const int* in_sizes, int n_in,
                              void* d_out, int out_size) {
    const float* x   = (const float*)d_in[0];
    const float* w1  = (const float*)d_in[1];
    const float* b1  = (const float*)d_in[2];
    const float* w2  = (const float*)d_in[3];
    const float* b2  = (const float*)d_in[4];
    const float* w3  = (const float*)d_in[5];
    const float* b3  = (const float*)d_in[6];
    const float* wd  = (const float*)d_in[7];
    const float* bd  = (const float*)d_in[8];
    const float* wp  = (const float*)d_in[9];
    const float* bp  = (const float*)d_in[10];
    const float* wf1 = (const float*)d_in[11];
    const float* bf1 = (const float*)d_in[12];
    const float* wf2 = (const float*)d_in[13];
    const float* bf2 = (const float*)d_in[14];
    const float* wf3 = (const float*)d_in[15];
    const float* bf3 = (const float*)d_in[16];
    float* out = (float*)d_out;

    const int c12_smem = C12_SMEM_FLOATS * (int)sizeof(float);
    const int c3_smem  = C3_SMEM_FLOATS  * (int)sizeof(float);
    const int dw_smem  = DW_SMEM_FLOATS  * (int)sizeof(float);
    cudaFuncSetAttribute(conv12_kernel, cudaFuncAttributeMaxDynamicSharedMemorySize, c12_smem);
    cudaFuncSetAttribute(conv3_kernel,  cudaFuncAttributeMaxDynamicSharedMemorySize, c3_smem);
    cudaFuncSetAttribute(dwpw_kernel,   cudaFuncAttributeMaxDynamicSharedMemorySize, dw_smem);

    // dummies shift the ncu capture slot (-s 5 -c 1) onto conv12
    warm_kernel<<<1, 32>>>();
    warm_kernel<<<1, 32>>>();
    warm_kernel<<<1, 32>>>();
    conv12_kernel<<<dim3(4, 4, BATCH), dim3(16, 16), c12_smem>>>(x, w1, b1, w2, b2);
    conv3_kernel<<<dim3(4, 4, BATCH), dim3(16, 16), c3_smem>>>(w3, b3);
    dwpw_kernel<<<dim3(4, 4, BATCH), dim3(16, 16), dw_smem>>>(wd, bd, wp, bp);
    phi_kernel<<<BATCH, 64>>>(wf1, bf1, wf2, bf2, wf3, bf3);
    grayblurh_kernel<<<dim3(256, BATCH), 256>>>(x, out);
    blurv_kernel<<<dim3(8, 4, BATCH), dim3(32, 8)>>>(out);
}

// round 16
// speedup vs baseline: 1.2090x; 1.2090x over previous
#include <cuda_runtime.h>

#define BATCH 64
#define H0 256
#define W0 256
#define H1 128
#define W1 128
#define NPIX0 (H0*W0)
#define NPIX1 (H1*W1)

typedef unsigned long long ull;

// ---- packed f32x2 helpers ----
__device__ __forceinline__ ull f2pack(float a, float b) {
    ull r; asm("mov.b64 %0, {%1, %2};" : "=l"(r) : "f"(a), "f"(b)); return r;
}
__device__ __forceinline__ void ffma2(ull& d, ull a, ull b) {
    asm("fma.rn.f32x2 %0, %1, %2, %0;" : "+l"(d) : "l"(a), "l"(b));
}
__device__ __forceinline__ float2 f2unpack(ull v) {
    float lo, hi; asm("mov.b64 {%0, %1}, %2;" : "=f"(lo), "=f"(hi) : "l"(v));
    return make_float2(lo, hi);
}
__device__ __forceinline__ ull f2packv(float2 v) { return f2pack(v.x, v.y); }

// ---- constant-bank weights (repacked at launch) -----------------------------
struct CW {
    float2 w1[27][8];     // [ic*9+ky*3+kx][oc pair]
    float2 w2[144][8];    // [ic*9+k][oc pair]
    float2 w3[144][8];
    float2 wp[16][8];     // [ic][oc pair]
    float  wd[16][9];
    float  b1[16], b2[16], b3[16], bd[16], bp[16];
};
__constant__ CW c_w;
__device__ CW g_stage;

__global__ void repack_kernel(const float* __restrict__ w1, const float* __restrict__ b1,
                              const float* __restrict__ w2, const float* __restrict__ b2,
                              const float* __restrict__ w3, const float* __restrict__ b3,
                              const float* __restrict__ wd, const float* __restrict__ bd,
                              const float* __restrict__ wp, const float* __restrict__ bp) {
    const int t = threadIdx.x;
    float* dst_w1 = (float*)g_stage.w1;
    for (int i = t; i < 27*16; i += 256) { int oc = i & 15, k = i >> 4; dst_w1[k*16 + oc] = w1[oc*27 + k]; }
    float* dst_w2 = (float*)g_stage.w2;
    for (int i = t; i < 144*16; i += 256) { int oc = i & 15, k = i >> 4; dst_w2[k*16 + oc] = w2[oc*144 + k]; }
    float* dst_w3 = (float*)g_stage.w3;
    for (int i = t; i < 144*16; i += 256) { int oc = i & 15, k = i >> 4; dst_w3[k*16 + oc] = w3[oc*144 + k]; }
    float* dst_wp = (float*)g_stage.wp;
    if (t < 256) { int oc = t >> 4, ic = t & 15; dst_wp[ic*16 + oc] = wp[oc*16 + ic]; }
    if (t < 144) ((float*)g_stage.wd)[t] = wd[t];
    if (t < 16) {
        g_stage.b1[t] = b1[t]; g_stage.b2[t] = b2[t]; g_stage.b3[t] = b3[t];
        g_stage.bd[t] = bd[t]; g_stage.bp[t] = bp[t];
    }
}

// ---------------- scratch (device globals: no allocations allowed) ----------
__device__ float g_t2[BATCH*16*NPIX1];    // conv2 out (67 MB)
__device__ float g_t3[BATCH*16*NPIX1];    // conv3 out (67 MB)
__device__ float g_part[BATCH*16*16];     // 32x32-block sums of fb (pool cells)
__device__ float g_phi[BATCH*3];          // combined head coefficients
__device__ float g_tmp[BATCH*NPIX0];      // horizontal blur intermediate (17 MB)

__global__ void warm_kernel() {}

// =====================================================================
// Fused conv1 (3->16, 3x3, s1, SAME, relu) + conv2 (16->16, 3x3, s2,
// SAME pad_lo=0, relu). One block -> 16x32 conv2 output tile; each
// thread owns 2 pixels (y, y+16). Weights from constant bank.
// =====================================================================
#define C12_SMEM_FLOATS (3*67*36 + 8*65*34)

__global__ void __launch_bounds__(256, 2)
conv12_kernel(const float* __restrict__ x) {
    extern __shared__ float sm[];
    float* s_x   = sm;                     // [3][67][36]  (67 rows x 35 cols used)
    float* s_mid = s_x + 3*67*36;          // [8][65][34]  (65 rows x 33 cols used)

    const int b = blockIdx.z;
    const int ox0 = blockIdx.x * 16, oy0 = blockIdx.y * 32;
    const int ix0 = ox0 * 2, iy0 = oy0 * 2;
    const int tid = threadIdx.y * 16 + threadIdx.x;
    const int ty = threadIdx.y, tx = threadIdx.x;

    // x halo: 3 x 67 x 35
    for (int i = tid; i < 3*67*35; i += 256) {
        int c = i / 2345, r = i % 2345;
        int yy = r / 35, xx = r % 35;
        int gy = iy0 + yy - 1, gx = ix0 + xx - 1;
        float v = 0.f;
        if (gy >= 0 && gy < H0 && gx >= 0 && gx < W0)
            v = x[((b*3 + c)*H0 + gy)*W0 + gx];
        s_x[(c*67 + yy)*36 + xx] = v;
    }

    ull accA[8], accB[8];
    #pragma unroll
    for (int j = 0; j < 8; j++) { accA[j] = 0ull; accB[j] = 0ull; }

    #pragma unroll
    for (int occ = 0; occ < 16; occ += 8) {
        const int p0 = occ >> 1;   // constant pair base
        __syncthreads();
        // ---- conv1 for channels occ..occ+7 over 65x33 positions, x-paired ----
        for (int i = tid; i < 65*17; i += 256) {
            const int yy = i / 17;
            const int xx0 = (i - yy*17) * 2;
            ull a0[4], a1[4];
            #pragma unroll
            for (int j = 0; j < 4; j++) {
                ull bb = f2pack(c_w.b1[occ + 2*j], c_w.b1[occ + 2*j + 1]);
                a0[j] = bb; a1[j] = bb;
            }
            #pragma unroll
            for (int c = 0; c < 3; c++)
                #pragma unroll
                for (int ky = 0; ky < 3; ky++) {
                    const float* rp = &s_x[(c*67 + yy + ky)*36 + xx0];
                    float2 q0 = *(const float2*)rp;
                    float2 q1 = *(const float2*)(rp + 2);
                    float v0 = q0.x, v1 = q0.y, v2 = q1.x, v3 = q1.y;
                    #pragma unroll
                    for (int kx = 0; kx < 3; kx++) {
                        float va = (kx == 0) ? v0 : (kx == 1 ? v1 : v2);
                        float vb = (kx == 0) ? v1 : (kx == 1 ? v2 : v3);
                        ull vba = f2pack(va, va);
                        ull vbb = f2pack(vb, vb);
                        const int tap = c*9 + ky*3 + kx;
                        ull wq0 = f2packv(c_w.w1[tap][p0 + 0]);
                        ull wq1 = f2packv(c_w.w1[tap][p0 + 1]);
                        ull wq2 = f2packv(c_w.w1[tap][p0 + 2]);
                        ull wq3 = f2packv(c_w.w1[tap][p0 + 3]);
                        ffma2(a0[0], vba, wq0); ffma2(a1[0], vbb, wq0);
                        ffma2(a0[1], vba, wq1); ffma2(a1[1], vbb, wq1);
                        ffma2(a0[2], vba, wq2); ffma2(a1[2], vbb, wq2);
                        ffma2(a0[3], vba, wq3); ffma2(a1[3], vbb, wq3);
                    }
                }
            const int gy1 = iy0 + yy;
            const int gx10 = ix0 + xx0;
            const bool v0ok = (gy1 < H0) && (gx10 < W0);
            const bool v1ok = (gy1 < H0) && (gx10 + 1 < W0);
            #pragma unroll
            for (int j = 0; j < 4; j++) {
                float2 r0 = f2unpack(a0[j]);
                float2 r1 = f2unpack(a1[j]);
                float2 stA = make_float2(v0ok ? fmaxf(r0.x, 0.f) : 0.f,
                                         v1ok ? fmaxf(r1.x, 0.f) : 0.f);
                float2 stB = make_float2(v0ok ? fmaxf(r0.y, 0.f) : 0.f,
                                         v1ok ? fmaxf(r1.y, 0.f) : 0.f);
                *(float2*)&s_mid[((2*j)*65 + yy)*34 + xx0]   = stA;
                *(float2*)&s_mid[((2*j+1)*65 + yy)*34 + xx0] = stB;
            }
        }
        __syncthreads();
        // ---- conv2 partial accumulation over these 8 input channels ----
        #pragma unroll 2
        for (int c = 0; c < 8; c++) {
            const float* base0 = &s_mid[(c*65 + 2*ty)*34 + 2*tx];
            const float* base1 = base0 + 32*34;
            float u0[3][3], u1[3][3];
            #pragma unroll
            for (int r = 0; r < 3; r++) {
                float2 qa = *(const float2*)&base0[r*34];
                u0[r][0] = qa.x; u0[r][1] = qa.y; u0[r][2] = base0[r*34 + 2];
                float2 qb = *(const float2*)&base1[r*34];
                u1[r][0] = qb.x; u1[r][1] = qb.y; u1[r][2] = base1[r*34 + 2];
            }
            #pragma unroll
            for (int ky = 0; ky < 3; ky++)
                #pragma unroll
                for (int kx = 0; kx < 3; kx++) {
                    const int tap = (occ + c)*9 + ky*3 + kx;
                    ull vA = f2pack(u0[ky][kx], u0[ky][kx]);
                    ull vB = f2pack(u1[ky][kx], u1[ky][kx]);
                    #pragma unroll
                    for (int j = 0; j < 8; j++) {
                        ull wq = f2packv(c_w.w2[tap][j]);
                        ffma2(accA[j], vA, wq);
                        ffma2(accB[j], vB, wq);
                    }
                }
        }
    }

    const int oyA = oy0 + ty, oyB = oy0 + ty + 16, ox = ox0 + tx;
    #pragma unroll
    for (int j = 0; j < 8; j++) {
        float2 a = f2unpack(accA[j]);
        float2 bq = f2unpack(accB[j]);
        g_t2[((b*16 + 2*j)*H1 + oyA)*W1 + ox]   = fmaxf(a.x + c_w.b2[2*j], 0.f);
        g_t2[((b*16 + 2*j+1)*H1 + oyA)*W1 + ox] = fmaxf(a.y + c_w.b2[2*j+1], 0.f);
        g_t2[((b*16 + 2*j)*H1 + oyB)*W1 + ox]   = fmaxf(bq.x + c_w.b2[2*j], 0.f);
        g_t2[((b*16 + 2*j+1)*H1 + oyB)*W1 + ox] = fmaxf(bq.y + c_w.b2[2*j+1], 0.f);
    }
}

// =====================================================================
// conv3: 16->16, 3x3, s1, SAME, relu. 32x32 tile, 2x2 pixels per thread.
// Weights from constant bank.
// =====================================================================
#define C3_SMEM_FLOATS (16*34*36)

__global__ void __launch_bounds__(256)
conv3_kernel() {
    extern __shared__ float sm[];
    float* s_in = sm;                 // [16][34][36]

    const int b = blockIdx.z;
    const int oy0 = blockIdx.y * 32, ox0 = blockIdx.x * 32;
    const int tid = threadIdx.y * 16 + threadIdx.x;
    const int ty = threadIdx.y, tx = threadIdx.x;

    for (int i = tid; i < 16*34*34; i += 256) {
        int c = i / 1156, r = i % 1156;
        int yy = r / 34, xx = r % 34;
        int gy = oy0 + yy - 1, gx = ox0 + xx - 1;
        float v = 0.f;
        if (gy >= 0 && gy < H1 && gx >= 0 && gx < W1)
            v = g_t2[((b*16 + c)*H1 + gy)*W1 + gx];
        s_in[(c*34 + yy)*36 + xx] = v;
    }
    __syncthreads();

    ull acc0[8], acc1[8], acc2[8], acc3[8];
    #pragma unroll
    for (int j = 0; j < 8; j++) {
        ull bb = f2pack(c_w.b3[2*j], c_w.b3[2*j+1]);
        acc0[j] = bb; acc1[j] = bb; acc2[j] = bb; acc3[j] = bb;
    }

    #pragma unroll 2
    for (int c = 0; c < 16; c++) {
        const float* base = &s_in[(c*34 + 2*ty)*36 + 2*tx];
        float vv[4][4];
        #pragma unroll
        for (int iy = 0; iy < 4; iy++) {
            float2 qa = *(const float2*)&base[iy*36];
            float2 qb = *(const float2*)&base[iy*36 + 2];
            vv[iy][0] = qa.x; vv[iy][1] = qa.y; vv[iy][2] = qb.x; vv[iy][3] = qb.y;
        }
        #pragma unroll
        for (int ky = 0; ky < 3; ky++)
            #pragma unroll
            for (int kx = 0; kx < 3; kx++) {
                const int tap = c*9 + ky*3 + kx;
                ull v00 = f2pack(vv[ky][kx],     vv[ky][kx]);
                ull v01 = f2pack(vv[ky][kx+1],   vv[ky][kx+1]);
                ull v10 = f2pack(vv[ky+1][kx],   vv[ky+1][kx]);
                ull v11 = f2pack(vv[ky+1][kx+1], vv[ky+1][kx+1]);
                #pragma unroll
                for (int j = 0; j < 8; j++) {
                    ull wq = f2packv(c_w.w3[tap][j]);
                    ffma2(acc0[j], v00, wq);
                    ffma2(acc1[j], v01, wq);
                    ffma2(acc2[j], v10, wq);
                    ffma2(acc3[j], v11, wq);
                }
            }
    }

    const int gy = oy0 + 2*ty, gx = ox0 + 2*tx;
    #pragma unroll
    for (int j = 0; j < 8; j++) {
        float2 a0 = f2unpack(acc0[j]), a1 = f2unpack(acc1[j]);
        float2 a2 = f2unpack(acc2[j]), a3 = f2unpack(acc3[j]);
        float* p0 = &g_t3[((b*16 + 2*j)*H1 + gy)*W1 + gx];
        *(float2*)p0        = make_float2(fmaxf(a0.x, 0.f), fmaxf(a1.x, 0.f));
        *(float2*)(p0 + W1) = make_float2(fmaxf(a2.x, 0.f), fmaxf(a3.x, 0.f));
        float* p1 = p0 + NPIX1;
        *(float2*)p1        = make_float2(fmaxf(a0.y, 0.f), fmaxf(a1.y, 0.f));
        *(float2*)(p1 + W1) = make_float2(fmaxf(a2.y, 0.f), fmaxf(a3.y, 0.f));
    }
}

// =====================================================================
// Fused depthwise 3x3 + relu + pointwise 1x1 + relu + 32x32 pool sum.
// Weights from constant bank.
// =====================================================================
#define DW_SMEM_FLOATS (16*34*36 + 128)

__global__ void __launch_bounds__(256)
dwpw_kernel() {
    extern __shared__ float sm[];
    float* s_in  = sm;                  // [16][34][36]
    float* s_red = s_in + 16*34*36;     // [8][16]

    const int b = blockIdx.z;
    const int oy0 = blockIdx.y * 32, ox0 = blockIdx.x * 32;
    const int tid = threadIdx.y * 16 + threadIdx.x;
    const int ty = threadIdx.y, tx = threadIdx.x;

    for (int i = tid; i < 16*34*34; i += 256) {
        int c = i / 1156, r = i % 1156;
        int yy = r / 34, xx = r % 34;
        int gy = oy0 + yy - 1, gx = ox0 + xx - 1;
        float v = 0.f;
        if (gy >= 0 && gy < H1 && gx >= 0 && gx < W1)
            v = g_t3[((b*16 + c)*H1 + gy)*W1 + gx];
        s_in[(c*34 + yy)*36 + xx] = v;
    }
    __syncthreads();

    ull acc0[8], acc1[8], acc2[8], acc3[8];
    #pragma unroll
    for (int j = 0; j < 8; j++) {
        ull bb = f2pack(c_w.bp[2*j], c_w.bp[2*j+1]);
        acc0[j] = bb; acc1[j] = bb; acc2[j] = bb; acc3[j] = bb;
    }

    #pragma unroll 2
    for (int c = 0; c < 16; c++) {
        const float* base = &s_in[(c*34 + 2*ty)*36 + 2*tx];
        float vv[4][4];
        #pragma unroll
        for (int iy = 0; iy < 4; iy++) {
            float2 qa = *(const float2*)&base[iy*36];
            float2 qb = *(const float2*)&base[iy*36 + 2];
            vv[iy][0] = qa.x; vv[iy][1] = qa.y; vv[iy][2] = qb.x; vv[iy][3] = qb.y;
        }
        ull d01 = f2pack(c_w.bd[c], c_w.bd[c]);
        ull d23 = d01;
        #pragma unroll
        for (int ky = 0; ky < 3; ky++)
            #pragma unroll
            for (int kx = 0; kx < 3; kx++) {
                float wvv = c_w.wd[c][ky*3 + kx];
                ull wb = f2pack(wvv, wvv);
                ull va = f2pack(vv[ky][kx],   vv[ky][kx+1]);
                ull vb = f2pack(vv[ky+1][kx], vv[ky+1][kx+1]);
                ffma2(d01, va, wb);
                ffma2(d23, vb, wb);
            }
        float2 dab = f2unpack(d01), dcd = f2unpack(d23);
        float dw0 = fmaxf(dab.x, 0.f), dw1 = fmaxf(dab.y, 0.f);
        float dw2 = fmaxf(dcd.x, 0.f), dw3 = fmaxf(dcd.y, 0.f);
        ull p0 = f2pack(dw0, dw0), p1 = f2pack(dw1, dw1);
        ull p2 = f2pack(dw2, dw2), p3 = f2pack(dw3, dw3);
        #pragma unroll
        for (int j = 0; j < 8; j++) {
            ull wq = f2packv(c_w.wp[c][j]);
            ffma2(acc0[j], p0, wq);
            ffma2(acc1[j], p1, wq);
            ffma2(acc2[j], p2, wq);
            ffma2(acc3[j], p3, wq);
        }
    }

    float t[16];
    #pragma unroll
    for (int j = 0; j < 8; j++) {
        float2 a0 = f2unpack(acc0[j]), a1 = f2unpack(acc1[j]);
        float2 a2 = f2unpack(acc2[j]), a3 = f2unpack(acc3[j]);
        t[2*j]   = fmaxf(a0.x,0.f) + fmaxf(a1.x,0.f) + fmaxf(a2.x,0.f) + fmaxf(a3.x,0.f);
        t[2*j+1] = fmaxf(a0.y,0.f) + fmaxf(a1.y,0.f) + fmaxf(a2.y,0.f) + fmaxf(a3.y,0.f);
    }
    #pragma unroll
    for (int oc = 0; oc < 16; oc++) {
        float v = t[oc];
        #pragma unroll
        for (int o = 16; o > 0; o >>= 1) v += __shfl_xor_sync(0xffffffffu, v, o);
        t[oc] = v;
    }
    const int warp = tid >> 5, lane = tid & 31;
    if (lane == 0) {
        #pragma unroll
        for (int oc = 0; oc < 16; oc++) s_red[warp*16 + oc] = t[oc];
    }
    __syncthreads();
    if (tid < 16) {
        float s = 0.f;
        #pragma unroll
        for (int w8 = 0; w8 < 8; w8++) s += s_red[w8*16 + tid];
        g_part[(b*16 + tid)*16 + blockIdx.y*4 + blockIdx.x] = s;
    }
}

// -------- combined head coefficients: phi = (phi1+phi2+phi3)/3 --------------
__global__ void phi_kernel(const float* __restrict__ wf1, const float* __restrict__ bf1,
                           const float* __restrict__ wf2, const float* __restrict__ bf2,
                           const float* __restrict__ wf3, const float* __restrict__ bf3) {
    const int b = blockIdx.x;
    const int t = threadIdx.x;
    const int c = t >> 4, ch = t & 15;
    __shared__ float red[48];
    float S = 0.f;
    if (t < 48) {
        const float* part = &g_part[(b*16 + ch)*16];
        float m[16];
        float sum16 = 0.f;
        #pragma unroll
        for (int p = 0; p < 16; p++) {
            m[p] = part[p] * (1.0f / 1024.0f);
            sum16 += m[p];
            S = fmaf(m[p], wf3[c*256 + ch*16 + p], S);
        }
        S = fmaf(sum16 * (1.f / 16.f), wf1[c*16 + ch], S);
        #pragma unroll
        for (int i = 0; i < 2; i++)
            #pragma unroll
            for (int j = 0; j < 2; j++) {
                float f2v = 0.25f * (m[(2*i)*4 + 2*j] + m[(2*i)*4 + 2*j + 1] +
                                     m[(2*i+1)*4 + 2*j] + m[(2*i+1)*4 + 2*j + 1]);
                S = fmaf(f2v, wf2[c*64 + ch*4 + i*2 + j], S);
            }
        red[t] = S;
    }
    __syncthreads();
    if (t < 3) {
        float tot = bf1[t] + bf2[t] + bf3[t];
        #pragma unroll
        for (int i = 0; i < 16; i++) tot += red[t*16 + i];
        g_phi[b*3 + t] = tot * (1.f / 3.f);
    }
}

// -------- fused grayscale + horizontal 21-tap Gaussian (reflect-101) --------
__global__ void grayblurh_kernel(const float* __restrict__ x, float* __restrict__ out) {
    __shared__ float row[256];
    __shared__ float sw[21];
    const int b = blockIdx.y, y = blockIdx.x;
    const int tx = threadIdx.x;
    if (tx < 21) {
        float t = (float)tx - 10.f;
        sw[tx] = expf(-(t * t) / 24.5f);
    }
    const float p0 = g_phi[b*3 + 0], p1 = g_phi[b*3 + 1], p2 = g_phi[b*3 + 2];
    const int i = y * 256 + tx;
    float v = p0 * x[(b*3 + 0)*NPIX0 + i]
            + p1 * x[(b*3 + 1)*NPIX0 + i]
            + p2 * x[(b*3 + 2)*NPIX0 + i];
    out[(b*3 + 1)*NPIX0 + i] = v;   // i_gray (channel 1)
    row[tx] = v;
    __syncthreads();
    float wsum = 0.f;
    #pragma unroll
    for (int t = 0; t < 21; t++) wsum += sw[t];
    float acc = 0.f;
    #pragma unroll
    for (int t = 0; t < 21; t++) {
        int xx = tx + t - 10;
        xx = xx < 0 ? -xx : (xx > 255 ? 510 - xx : xx);
        acc = fmaf(sw[t], row[xx], acc);
    }
    g_tmp[(b*256 + y)*256 + tx] = acc / wsum;
}

// -------- vertical 21-tap Gaussian + base/detail writes ---------------------
__global__ void blurv_kernel(float* __restrict__ out) {
    __shared__ float tile[84][32];
    __shared__ float sw[21];
    const int b = blockIdx.z;
    const int x0 = blockIdx.x * 32, y0 = blockIdx.y * 64;
    const int tid = threadIdx.y * 32 + threadIdx.x;
    if (tid < 21) {
        float t = (float)tid - 10.f;
        sw[tid] = expf(-(t * t) / 24.5f);
    }
    for (int i = tid; i < 84 * 32; i += 256) {
        int yy = i >> 5, xx = i & 31;
        int gy = y0 + yy - 10;
        gy = gy < 0 ? -gy : (gy > 255 ? 510 - gy : gy);
        tile[yy][xx] = g_tmp[(b*256 + gy)*256 + x0 + xx];
    }
    __syncthreads();
    float wsum = 0.f;
    #pragma unroll
    for (int t = 0; t < 21; t++) wsum += sw[t];
    const float inv = 1.f / wsum;
    const int tx = threadIdx.x;
    for (int r = 0; r < 8; r++) {
        const int ly = threadIdx.y * 8 + r;
        float acc = 0.f;
        #pragma unroll
        for (int t = 0; t < 21; t++) acc = fmaf(sw[t], tile[ly + t][tx], acc);
        const float base = acc * inv;
        const int gy = y0 + ly, gx = x0 + tx;
        const int idx = (b*3)*NPIX0 + gy*256 + gx;
        const float ig = out[idx + NPIX0];
        out[idx] = base;                  // base   (channel 0)
        out[idx + 2*NPIX0] = ig - base;   // detail (channel 2)
    }
}

// ---------------------------------------------------------------------------
extern "C" void kernel_launch(void* const* d_in, const int* in_sizes, int n_in,
                              void* d_out, int out_size) {
    const float* x   = (const float*)d_in[0];
    const float* w1  = (const float*)d_in[1];
    const float* b1  = (const float*)d_in[2];
    const float* w2  = (const float*)d_in[3];
    const float* b2  = (const float*)d_in[4];
    const float* w3  = (const float*)d_in[5];
    const float* b3  = (const float*)d_in[6];
    const float* wd  = (const float*)d_in[7];
    const float* bd  = (const float*)d_in[8];
    const float* wp  = (const float*)d_in[9];
    const float* bp  = (const float*)d_in[10];
    const float* wf1 = (const float*)d_in[11];
    const float* bf1 = (const float*)d_in[12];
    const float* wf2 = (const float*)d_in[13];
    const float* bf2 = (const float*)d_in[14];
    const float* wf3 = (const float*)d_in[15];
    const float* bf3 = (const float*)d_in[16];
    float* out = (float*)d_out;

    const int c12_smem = C12_SMEM_FLOATS * (int)sizeof(float);
    const int c3_smem  = C3_SMEM_FLOATS  * (int)sizeof(float);
    const int dw_smem  = DW_SMEM_FLOATS  * (int)sizeof(float);
    cudaFuncSetAttribute(conv12_kernel, cudaFuncAttributeMaxDynamicSharedMemorySize, c12_smem);
    cudaFuncSetAttribute(conv3_kernel,  cudaFuncAttributeMaxDynamicSharedMemorySize, c3_smem);
    cudaFuncSetAttribute(dwpw_kernel,   cudaFuncAttributeMaxDynamicSharedMemorySize, dw_smem);

    void* stage_ptr = nullptr;
    cudaGetSymbolAddress(&stage_ptr, g_stage);

    // repack weights -> staging -> constant bank (all graph-capturable)
    repack_kernel<<<1, 256>>>(w1, b1, w2, b2, w3, b3, wd, bd, wp, bp);
    cudaMemcpyToSymbolAsync(c_w, stage_ptr, sizeof(CW), 0, cudaMemcpyDeviceToDevice, 0);

    // keep the ncu capture slot (-s 5 -c 1) on conv12: 2 harness + repack + 2 warm
    warm_kernel<<<1, 32>>>();
    warm_kernel<<<1, 32>>>();
    conv12_kernel<<<dim3(8, 4, BATCH), dim3(16, 16), c12_smem>>>(x);
    conv3_kernel<<<dim3(4, 4, BATCH), dim3(16, 16), c3_smem>>>();
    dwpw_kernel<<<dim3(4, 4, BATCH), dim3(16, 16), dw_smem>>>();
    phi_kernel<<<BATCH, 64>>>(wf1, bf1, wf2, bf2, wf3, bf3);
    grayblurh_kernel<<<dim3(256, BATCH), 256>>>(x, out);
    blurv_kernel<<<dim3(8, 4, BATCH), dim3(32, 8)>>>(out);
}

// round 17
// speedup vs baseline: 1.2190x; 1.0083x over previous
#include <cuda_runtime.h>

#define BATCH 64
#define H0 256
#define W0 256
#define H1 128
#define W1 128
#define NPIX0 (H0*W0)
#define NPIX1 (H1*W1)

typedef unsigned long long ull;

// ---- packed f32x2 helpers ----
__device__ __forceinline__ ull f2pack(float a, float b) {
    ull r; asm("mov.b64 %0, {%1, %2};" : "=l"(r) : "f"(a), "f"(b)); return r;
}
__device__ __forceinline__ void ffma2(ull& d, ull a, ull b) {
    asm("fma.rn.f32x2 %0, %1, %2, %0;" : "+l"(d) : "l"(a), "l"(b));
}
__device__ __forceinline__ float2 f2unpack(ull v) {
    float lo, hi; asm("mov.b64 {%0, %1}, %2;" : "=f"(lo), "=f"(hi) : "l"(v));
    return make_float2(lo, hi);
}
__device__ __forceinline__ ull f2packv(float2 v) { return f2pack(v.x, v.y); }

// ---- constant-bank weights (repacked at launch) -----------------------------
struct CW {
    float2 w1[27][8];     // [ic*9+ky*3+kx][oc pair]
    float2 w2[144][8];    // [ic*9+k][oc pair]
    float2 w3[144][8];
    float2 wp[16][8];     // [ic][oc pair]
    float  wd[16][9];
    float  b1[16], b2[16], b3[16], bd[16], bp[16];
};
__constant__ CW c_w;
__device__ CW g_stage;

__global__ void repack_kernel(const float* __restrict__ w1, const float* __restrict__ b1,
                              const float* __restrict__ w2, const float* __restrict__ b2,
                              const float* __restrict__ w3, const float* __restrict__ b3,
                              const float* __restrict__ wd, const float* __restrict__ bd,
                              const float* __restrict__ wp, const float* __restrict__ bp) {
    const int t = threadIdx.x;
    float* dst_w1 = (float*)g_stage.w1;
    for (int i = t; i < 27*16; i += 256) { int oc = i & 15, k = i >> 4; dst_w1[k*16 + oc] = w1[oc*27 + k]; }
    float* dst_w2 = (float*)g_stage.w2;
    for (int i = t; i < 144*16; i += 256) { int oc = i & 15, k = i >> 4; dst_w2[k*16 + oc] = w2[oc*144 + k]; }
    float* dst_w3 = (float*)g_stage.w3;
    for (int i = t; i < 144*16; i += 256) { int oc = i & 15, k = i >> 4; dst_w3[k*16 + oc] = w3[oc*144 + k]; }
    float* dst_wp = (float*)g_stage.wp;
    if (t < 256) { int oc = t >> 4, ic = t & 15; dst_wp[ic*16 + oc] = wp[oc*16 + ic]; }
    if (t < 144) ((float*)g_stage.wd)[t] = wd[t];
    if (t < 16) {
        g_stage.b1[t] = b1[t]; g_stage.b2[t] = b2[t]; g_stage.b3[t] = b3[t];
        g_stage.bd[t] = bd[t]; g_stage.bp[t] = bp[t];
    }
}

// ---------------- scratch (device globals: no allocations allowed) ----------
__device__ float g_t2[BATCH*16*NPIX1];    // conv2 out (67 MB)
__device__ float g_t3[BATCH*16*NPIX1];    // conv3 out (67 MB)
__device__ float g_part[BATCH*16*16];     // 32x32-block sums of fb (pool cells)
__device__ float g_phi[BATCH*3];          // combined head coefficients
__device__ float g_tmp[BATCH*NPIX0];      // horizontal blur intermediate (17 MB)

__global__ void warm_kernel() {}

// =====================================================================
// Fused conv1 (3->16, 3x3, s1, SAME, relu) + conv2 (16->16, 3x3, s2,
// SAME pad_lo=0, relu). One block -> 16x32 conv2 output tile; each
// thread owns 2 pixels (y, y+16). Weights from constant bank.
// s_mid split into 4-channel chunks -> 64.3 KB smem -> 3 CTAs/SM.
// =====================================================================
#define C12_SMEM_FLOATS (3*67*36 + 4*65*34)

__global__ void __launch_bounds__(256, 3)
conv12_kernel(const float* __restrict__ x) {
    extern __shared__ float sm[];
    float* s_x   = sm;                     // [3][67][36]  (67 rows x 35 cols used)
    float* s_mid = s_x + 3*67*36;          // [4][65][34]  (65 rows x 33 cols used)

    const int b = blockIdx.z;
    const int ox0 = blockIdx.x * 16, oy0 = blockIdx.y * 32;
    const int ix0 = ox0 * 2, iy0 = oy0 * 2;
    const int tid = threadIdx.y * 16 + threadIdx.x;
    const int ty = threadIdx.y, tx = threadIdx.x;

    // x halo: 3 x 67 x 35
    for (int i = tid; i < 3*67*35; i += 256) {
        int c = i / 2345, r = i % 2345;
        int yy = r / 35, xx = r % 35;
        int gy = iy0 + yy - 1, gx = ix0 + xx - 1;
        float v = 0.f;
        if (gy >= 0 && gy < H0 && gx >= 0 && gx < W0)
            v = x[((b*3 + c)*H0 + gy)*W0 + gx];
        s_x[(c*67 + yy)*36 + xx] = v;
    }

    ull accA[8], accB[8];
    #pragma unroll
    for (int j = 0; j < 8; j++) { accA[j] = 0ull; accB[j] = 0ull; }

    #pragma unroll
    for (int occ = 0; occ < 16; occ += 4) {
        const int p0 = occ >> 1;   // constant pair base (steps 0,2,4,6)
        __syncthreads();
        // ---- conv1 for channels occ..occ+3 over 65x33 positions, x-paired ----
        for (int i = tid; i < 65*17; i += 256) {
            const int yy = i / 17;
            const int xx0 = (i - yy*17) * 2;
            ull a0[2], a1[2];
            #pragma unroll
            for (int j = 0; j < 2; j++) {
                ull bb = f2pack(c_w.b1[occ + 2*j], c_w.b1[occ + 2*j + 1]);
                a0[j] = bb; a1[j] = bb;
            }
            #pragma unroll
            for (int c = 0; c < 3; c++)
                #pragma unroll
                for (int ky = 0; ky < 3; ky++) {
                    const float* rp = &s_x[(c*67 + yy + ky)*36 + xx0];
                    float2 q0 = *(const float2*)rp;
                    float2 q1 = *(const float2*)(rp + 2);
                    float v0 = q0.x, v1 = q0.y, v2 = q1.x, v3 = q1.y;
                    #pragma unroll
                    for (int kx = 0; kx < 3; kx++) {
                        float va = (kx == 0) ? v0 : (kx == 1 ? v1 : v2);
                        float vb = (kx == 0) ? v1 : (kx == 1 ? v2 : v3);
                        ull vba = f2pack(va, va);
                        ull vbb = f2pack(vb, vb);
                        const int tap = c*9 + ky*3 + kx;
                        ull wq0 = f2packv(c_w.w1[tap][p0 + 0]);
                        ull wq1 = f2packv(c_w.w1[tap][p0 + 1]);
                        ffma2(a0[0], vba, wq0); ffma2(a1[0], vbb, wq0);
                        ffma2(a0[1], vba, wq1); ffma2(a1[1], vbb, wq1);
                    }
                }
            const int gy1 = iy0 + yy;
            const int gx10 = ix0 + xx0;
            const bool v0ok = (gy1 < H0) && (gx10 < W0);
            const bool v1ok = (gy1 < H0) && (gx10 + 1 < W0);
            #pragma unroll
            for (int j = 0; j < 2; j++) {
                float2 r0 = f2unpack(a0[j]);
                float2 r1 = f2unpack(a1[j]);
                float2 stA = make_float2(v0ok ? fmaxf(r0.x, 0.f) : 0.f,
                                         v1ok ? fmaxf(r1.x, 0.f) : 0.f);
                float2 stB = make_float2(v0ok ? fmaxf(r0.y, 0.f) : 0.f,
                                         v1ok ? fmaxf(r1.y, 0.f) : 0.f);
                *(float2*)&s_mid[((2*j)*65 + yy)*34 + xx0]   = stA;
                *(float2*)&s_mid[((2*j+1)*65 + yy)*34 + xx0] = stB;
            }
        }
        __syncthreads();
        // ---- conv2 partial accumulation over these 4 input channels ----
        #pragma unroll
        for (int c = 0; c < 4; c++) {
            const float* base0 = &s_mid[(c*65 + 2*ty)*34 + 2*tx];
            const float* base1 = base0 + 32*34;
            float u0[3][3], u1[3][3];
            #pragma unroll
            for (int r = 0; r < 3; r++) {
                float2 qa = *(const float2*)&base0[r*34];
                u0[r][0] = qa.x; u0[r][1] = qa.y; u0[r][2] = base0[r*34 + 2];
                float2 qb = *(const float2*)&base1[r*34];
                u1[r][0] = qb.x; u1[r][1] = qb.y; u1[r][2] = base1[r*34 + 2];
            }
            #pragma unroll
            for (int ky = 0; ky < 3; ky++)
                #pragma unroll
                for (int kx = 0; kx < 3; kx++) {
                    const int tap = (occ + c)*9 + ky*3 + kx;
                    ull vA = f2pack(u0[ky][kx], u0[ky][kx]);
                    ull vB = f2pack(u1[ky][kx], u1[ky][kx]);
                    #pragma unroll
                    for (int j = 0; j < 8; j++) {
                        ull wq = f2packv(c_w.w2[tap][j]);
                        ffma2(accA[j], vA, wq);
                        ffma2(accB[j], vB, wq);
                    }
                }
        }
    }

    const int oyA = oy0 + ty, oyB = oy0 + ty + 16, ox = ox0 + tx;
    #pragma unroll
    for (int j = 0; j < 8; j++) {
        float2 a = f2unpack(accA[j]);
        float2 bq = f2unpack(accB[j]);
        g_t2[((b*16 + 2*j)*H1 + oyA)*W1 + ox]   = fmaxf(a.x + c_w.b2[2*j], 0.f);
        g_t2[((b*16 + 2*j+1)*H1 + oyA)*W1 + ox] = fmaxf(a.y + c_w.b2[2*j+1], 0.f);
        g_t2[((b*16 + 2*j)*H1 + oyB)*W1 + ox]   = fmaxf(bq.x + c_w.b2[2*j], 0.f);
        g_t2[((b*16 + 2*j+1)*H1 + oyB)*W1 + ox] = fmaxf(bq.y + c_w.b2[2*j+1], 0.f);
    }
}

// =====================================================================
// conv3: 16->16, 3x3, s1, SAME, relu. 32x32 tile, 2x2 pixels per thread.
// Weights from constant bank.
// =====================================================================
#define C3_SMEM_FLOATS (16*34*36)

__global__ void __launch_bounds__(256)
conv3_kernel() {
    extern __shared__ float sm[];
    float* s_in = sm;                 // [16][34][36]

    const int b = blockIdx.z;
    const int oy0 = blockIdx.y * 32, ox0 = blockIdx.x * 32;
    const int tid = threadIdx.y * 16 + threadIdx.x;
    const int ty = threadIdx.y, tx = threadIdx.x;

    for (int i = tid; i < 16*34*34; i += 256) {
        int c = i / 1156, r = i % 1156;
        int yy = r / 34, xx = r % 34;
        int gy = oy0 + yy - 1, gx = ox0 + xx - 1;
        float v = 0.f;
        if (gy >= 0 && gy < H1 && gx >= 0 && gx < W1)
            v = g_t2[((b*16 + c)*H1 + gy)*W1 + gx];
        s_in[(c*34 + yy)*36 + xx] = v;
    }
    __syncthreads();

    ull acc0[8], acc1[8], acc2[8], acc3[8];
    #pragma unroll
    for (int j = 0; j < 8; j++) {
        ull bb = f2pack(c_w.b3[2*j], c_w.b3[2*j+1]);
        acc0[j] = bb; acc1[j] = bb; acc2[j] = bb; acc3[j] = bb;
    }

    #pragma unroll 2
    for (int c = 0; c < 16; c++) {
        const float* base = &s_in[(c*34 + 2*ty)*36 + 2*tx];
        float vv[4][4];
        #pragma unroll
        for (int iy = 0; iy < 4; iy++) {
            float2 qa = *(const float2*)&base[iy*36];
            float2 qb = *(const float2*)&base[iy*36 + 2];
            vv[iy][0] = qa.x; vv[iy][1] = qa.y; vv[iy][2] = qb.x; vv[iy][3] = qb.y;
        }
        #pragma unroll
        for (int ky = 0; ky < 3; ky++)
            #pragma unroll
            for (int kx = 0; kx < 3; kx++) {
                const int tap = c*9 + ky*3 + kx;
                ull v00 = f2pack(vv[ky][kx],     vv[ky][kx]);
                ull v01 = f2pack(vv[ky][kx+1],   vv[ky][kx+1]);
                ull v10 = f2pack(vv[ky+1][kx],   vv[ky+1][kx]);
                ull v11 = f2pack(vv[ky+1][kx+1], vv[ky+1][kx+1]);
                #pragma unroll
                for (int j = 0; j < 8; j++) {
                    ull wq = f2packv(c_w.w3[tap][j]);
                    ffma2(acc0[j], v00, wq);
                    ffma2(acc1[j], v01, wq);
                    ffma2(acc2[j], v10, wq);
                    ffma2(acc3[j], v11, wq);
                }
            }
    }

    const int gy = oy0 + 2*ty, gx = ox0 + 2*tx;
    #pragma unroll
    for (int j = 0; j < 8; j++) {
        float2 a0 = f2unpack(acc0[j]), a1 = f2unpack(acc1[j]);
        float2 a2 = f2unpack(acc2[j]), a3 = f2unpack(acc3[j]);
        float* p0 = &g_t3[((b*16 + 2*j)*H1 + gy)*W1 + gx];
        *(float2*)p0        = make_float2(fmaxf(a0.x, 0.f), fmaxf(a1.x, 0.f));
        *(float2*)(p0 + W1) = make_float2(fmaxf(a2.x, 0.f), fmaxf(a3.x, 0.f));
        float* p1 = p0 + NPIX1;
        *(float2*)p1        = make_float2(fmaxf(a0.y, 0.f), fmaxf(a1.y, 0.f));
        *(float2*)(p1 + W1) = make_float2(fmaxf(a2.y, 0.f), fmaxf(a3.y, 0.f));
    }
}

// =====================================================================
// Fused depthwise 3x3 + relu + pointwise 1x1 + relu + 32x32 pool sum.
// Weights from constant bank.
// =====================================================================
#define DW_SMEM_FLOATS (16*34*36 + 128)

__global__ void __launch_bounds__(256)
dwpw_kernel() {
    extern __shared__ float sm[];
    float* s_in  = sm;                  // [16][34][36]
    float* s_red = s_in + 16*34*36;     // [8][16]

    const int b = blockIdx.z;
    const int oy0 = blockIdx.y * 32, ox0 = blockIdx.x * 32;
    const int tid = threadIdx.y * 16 + threadIdx.x;
    const int ty = threadIdx.y, tx = threadIdx.x;

    for (int i = tid; i < 16*34*34; i += 256) {
        int c = i / 1156, r = i % 1156;
        int yy = r / 34, xx = r % 34;
        int gy = oy0 + yy - 1, gx = ox0 + xx - 1;
        float v = 0.f;
        if (gy >= 0 && gy < H1 && gx >= 0 && gx < W1)
            v = g_t3[((b*16 + c)*H1 + gy)*W1 + gx];
        s_in[(c*34 + yy)*36 + xx] = v;
    }
    __syncthreads();

    ull acc0[8], acc1[8], acc2[8], acc3[8];
    #pragma unroll
    for (int j = 0; j < 8; j++) {
        ull bb = f2pack(c_w.bp[2*j], c_w.bp[2*j+1]);
        acc0[j] = bb; acc1[j] = bb; acc2[j] = bb; acc3[j] = bb;
    }

    #pragma unroll 2
    for (int c = 0; c < 16; c++) {
        const float* base = &s_in[(c*34 + 2*ty)*36 + 2*tx];
        float vv[4][4];
        #pragma unroll
        for (int iy = 0; iy < 4; iy++) {
            float2 qa = *(const float2*)&base[iy*36];
            float2 qb = *(const float2*)&base[iy*36 + 2];
            vv[iy][0] = qa.x; vv[iy][1] = qa.y; vv[iy][2] = qb.x; vv[iy][3] = qb.y;
        }
        ull d01 = f2pack(c_w.bd[c], c_w.bd[c]);
        ull d23 = d01;
        #pragma unroll
        for (int ky = 0; ky < 3; ky++)
            #pragma unroll
            for (int kx = 0; kx < 3; kx++) {
                float wvv = c_w.wd[c][ky*3 + kx];
                ull wb = f2pack(wvv, wvv);
                ull va = f2pack(vv[ky][kx],   vv[ky][kx+1]);
                ull vb = f2pack(vv[ky+1][kx], vv[ky+1][kx+1]);
                ffma2(d01, va, wb);
                ffma2(d23, vb, wb);
            }
        float2 dab = f2unpack(d01), dcd = f2unpack(d23);
        float dw0 = fmaxf(dab.x, 0.f), dw1 = fmaxf(dab.y, 0.f);
        float dw2 = fmaxf(dcd.x, 0.f), dw3 = fmaxf(dcd.y, 0.f);
        ull p0 = f2pack(dw0, dw0), p1 = f2pack(dw1, dw1);
        ull p2 = f2pack(dw2, dw2), p3 = f2pack(dw3, dw3);
        #pragma unroll
        for (int j = 0; j < 8; j++) {
            ull wq = f2packv(c_w.wp[c][j]);
            ffma2(acc0[j], p0, wq);
            ffma2(acc1[j], p1, wq);
            ffma2(acc2[j], p2, wq);
            ffma2(acc3[j], p3, wq);
        }
    }

    float t[16];
    #pragma unroll
    for (int j = 0; j < 8; j++) {
        float2 a0 = f2unpack(acc0[j]), a1 = f2unpack(acc1[j]);
        float2 a2 = f2unpack(acc2[j]), a3 = f2unpack(acc3[j]);
        t[2*j]   = fmaxf(a0.x,0.f) + fmaxf(a1.x,0.f) + fmaxf(a2.x,0.f) + fmaxf(a3.x,0.f);
        t[2*j+1] = fmaxf(a0.y,0.f) + fmaxf(a1.y,0.f) + fmaxf(a2.y,0.f) + fmaxf(a3.y,0.f);
    }
    #pragma unroll
    for (int oc = 0; oc < 16; oc++) {
        float v = t[oc];
        #pragma unroll
        for (int o = 16; o > 0; o >>= 1) v += __shfl_xor_sync(0xffffffffu, v, o);
        t[oc] = v;
    }
    const int warp = tid >> 5, lane = tid & 31;
    if (lane == 0) {
        #pragma unroll
        for (int oc = 0; oc < 16; oc++) s_red[warp*16 + oc] = t[oc];
    }
    __syncthreads();
    if (tid < 16) {
        float s = 0.f;
        #pragma unroll
        for (int w8 = 0; w8 < 8; w8++) s += s_red[w8*16 + tid];
        g_part[(b*16 + tid)*16 + blockIdx.y*4 + blockIdx.x] = s;
    }
}

// -------- combined head coefficients: phi = (phi1+phi2+phi3)/3 --------------
__global__ void phi_kernel(const float* __restrict__ wf1, const float* __restrict__ bf1,
                           const float* __restrict__ wf2, const float* __restrict__ bf2,
                           const float* __restrict__ wf3, const float* __restrict__ bf3) {
    const int b = blockIdx.x;
    const int t = threadIdx.x;
    const int c = t >> 4, ch = t & 15;
    __shared__ float red[48];
    float S = 0.f;
    if (t < 48) {
        const float* part = &g_part[(b*16 + ch)*16];
        float m[16];
        float sum16 = 0.f;
        #pragma unroll
        for (int p = 0; p < 16; p++) {
            m[p] = part[p] * (1.0f / 1024.0f);
            sum16 += m[p];
            S = fmaf(m[p], wf3[c*256 + ch*16 + p], S);
        }
        S = fmaf(sum16 * (1.f / 16.f), wf1[c*16 + ch], S);
        #pragma unroll
        for (int i = 0; i < 2; i++)
            #pragma unroll
            for (int j = 0; j < 2; j++) {
                float f2v = 0.25f * (m[(2*i)*4 + 2*j] + m[(2*i)*4 + 2*j + 1] +
                                     m[(2*i+1)*4 + 2*j] + m[(2*i+1)*4 + 2*j + 1]);
                S = fmaf(f2v, wf2[c*64 + ch*4 + i*2 + j], S);
            }
        red[t] = S;
    }
    __syncthreads();
    if (t < 3) {
        float tot = bf1[t] + bf2[t] + bf3[t];
        #pragma unroll
        for (int i = 0; i < 16; i++) tot += red[t*16 + i];
        g_phi[b*3 + t] = tot * (1.f / 3.f);
    }
}

// -------- fused grayscale + horizontal 21-tap Gaussian (reflect-101) --------
__global__ void grayblurh_kernel(const float* __restrict__ x, float* __restrict__ out) {
    __shared__ float row[256];
    __shared__ float sw[21];
    const int b = blockIdx.y, y = blockIdx.x;
    const int tx = threadIdx.x;
    if (tx < 21) {
        float t = (float)tx - 10.f;
        sw[tx] = expf(-(t * t) / 24.5f);
    }
    const float p0 = g_phi[b*3 + 0], p1 = g_phi[b*3 + 1], p2 = g_phi[b*3 + 2];
    const int i = y * 256 + tx;
    float v = p0 * x[(b*3 + 0)*NPIX0 + i]
            + p1 * x[(b*3 + 1)*NPIX0 + i]
            + p2 * x[(b*3 + 2)*NPIX0 + i];
    out[(b*3 + 1)*NPIX0 + i] = v;   // i_gray (channel 1)
    row[tx] = v;
    __syncthreads();
    float wsum = 0.f;
    #pragma unroll
    for (int t = 0; t < 21; t++) wsum += sw[t];
    float acc = 0.f;
    #pragma unroll
    for (int t = 0; t < 21; t++) {
        int xx = tx + t - 10;
        xx = xx < 0 ? -xx : (xx > 255 ? 510 - xx : xx);
        acc = fmaf(sw[t], row[xx], acc);
    }
    g_tmp[(b*256 + y)*256 + tx] = acc / wsum;
}

// -------- vertical 21-tap Gaussian + base/detail writes ---------------------
__global__ void blurv_kernel(float* __restrict__ out) {
    __shared__ float tile[84][32];
    __shared__ float sw[21];
    const int b = blockIdx.z;
    const int x0 = blockIdx.x * 32, y0 = blockIdx.y * 64;
    const int tid = threadIdx.y * 32 + threadIdx.x;
    if (tid < 21) {
        float t = (float)tid - 10.f;
        sw[tid] = expf(-(t * t) / 24.5f);
    }
    for (int i = tid; i < 84 * 32; i += 256) {
        int yy = i >> 5, xx = i & 31;
        int gy = y0 + yy - 10;
        gy = gy < 0 ? -gy : (gy > 255 ? 510 - gy : gy);
        tile[yy][xx] = g_tmp[(b*256 + gy)*256 + x0 + xx];
    }
    __syncthreads();
    float wsum = 0.f;
    #pragma unroll
    for (int t = 0; t < 21; t++) wsum += sw[t];
    const float inv = 1.f / wsum;
    const int tx = threadIdx.x;
    for (int r = 0; r < 8; r++) {
        const int ly = threadIdx.y * 8 + r;
        float acc = 0.f;
        #pragma unroll
        for (int t = 0; t < 21; t++) acc = fmaf(sw[t], tile[ly + t][tx], acc);
        const float base = acc * inv;
        const int gy = y0 + ly, gx = x0 + tx;
        const int idx = (b*3)*NPIX0 + gy*256 + gx;
        const float ig = out[idx + NPIX0];
        out[idx] = base;                  // base   (channel 0)
        out[idx + 2*NPIX0] = ig - base;   // detail (channel 2)
    }
}

// ---------------------------------------------------------------------------
extern "C" void kernel_launch(void* const* d_in, const int* in_sizes, int n_in,
                              void* d_out, int out_size) {
    const float* x   = (const float*)d_in[0];
    const float* w1  = (const float*)d_in[1];
    const float* b1  = (const float*)d_in[2];
    const float* w2  = (const float*)d_in[3];
    const float* b2  = (const float*)d_in[4];
    const float* w3  = (const float*)d_in[5];
    const float* b3  = (const float*)d_in[6];
    const float* wd  = (const float*)d_in[7];
    const float* bd  = (const float*)d_in[8];
    const float* wp  = (const float*)d_in[9];
    const float* bp  = (const float*)d_in[10];
    const float* wf1 = (const float*)d_in[11];
    const float* bf1 = (const float*)d_in[12];
    const float* wf2 = (const float*)d_in[13];
    const float* bf2 = (const float*)d_in[14];
    const float* wf3 = (const float*)d_in[15];
    const float* bf3 = (const float*)d_in[16];
    float* out = (float*)d_out;

    const int c12_smem = C12_SMEM_FLOATS * (int)sizeof(float);
    const int c3_smem  = C3_SMEM_FLOATS  * (int)sizeof(float);
    const int dw_smem  = DW_SMEM_FLOATS  * (int)sizeof(float);
    cudaFuncSetAttribute(conv12_kernel, cudaFuncAttributeMaxDynamicSharedMemorySize, c12_smem);
    cudaFuncSetAttribute(conv3_kernel,  cudaFuncAttributeMaxDynamicSharedMemorySize, c3_smem);
    cudaFuncSetAttribute(dwpw_kernel,   cudaFuncAttributeMaxDynamicSharedMemorySize, dw_smem);

    void* stage_ptr = nullptr;
    cudaGetSymbolAddress(&stage_ptr, g_stage);

    // repack weights -> staging -> constant bank (all graph-capturable)
    repack_kernel<<<1, 256>>>(w1, b1, w2, b2, w3, b3, wd, bd, wp, bp);
    cudaMemcpyToSymbolAsync(c_w, stage_ptr, sizeof(CW), 0, cudaMemcpyDeviceToDevice, 0);

    // keep the ncu capture slot (-s 5 -c 1) on conv12: 2 harness + repack + 2 warm
    warm_kernel<<<1, 32>>>();
    warm_kernel<<<1, 32>>>();
    conv12_kernel<<<dim3(8, 4, BATCH), dim3(16, 16), c12_smem>>>(x);
    conv3_kernel<<<dim3(4, 4, BATCH), dim3(16, 16), c3_smem>>>();
    dwpw_kernel<<<dim3(4, 4, BATCH), dim3(16, 16), dw_smem>>>();
    phi_kernel<<<BATCH, 64>>>(wf1, bf1, wf2, bf2, wf3, bf3);
    grayblurh_kernel<<<dim3(256, BATCH), 256>>>(x, out);
    blurv_kernel<<<dim3(8, 4, BATCH), dim3(32, 8)>>>(out);
}